// round 10
// baseline (speedup 1.0000x reference)
#include <cuda_runtime.h>
#include <cuda_bf16.h>
#include <cstdint>

// NeuralNetwork_28819230556388 — B=262144, D=64, 13 chained 64x64 GEMMs.
// R10: bf16 3-product split (rel_err ~6e-6), 2 warps/SMSP, TWO 16-row groups
// per warp with B-fragments shared across groups (LDSM per MAC halved, GEMM
// bursts doubled) to raise tensor-pipe duty cycle against warp convoying.
// Weights SMEM-resident, activations register-resident (2 slots per group,
// in-place rotation), persistent CTAs, no barriers in the main loop.

#define TPB     256
#define GRID    148
#define NMAC    8192                  // 262144 / 32 rows per macro-group
#define WSTEP   (GRID * (TPB / 32))   // 1184 warps

// SMEM layout (bytes)
#define OFF_BN 0                     // 7*64 f32 = 1792
#define OFF_BS 1792                  // 6*64 f32 = 1536
#define OFF_W  4096                  // 13 mats * 16384 (hi at +0, lo at +8192)
#define SMEM_TOTAL (4096 + 26*8192)  // 217088

#define SMEM_SWIZZLE_128B(bo) ((bo) ^ (((bo) >> 3) & 0x70))

__device__ __forceinline__ uint32_t smem_to_u32(const void* p) {
    uint32_t a;
    asm("{ .reg .u64 t; cvta.to.shared.u64 t, %1; cvt.u32.u64 %0, t; }"
        : "=r"(a) : "l"(p));
    return a;
}

#define LDSM_X4(r, addr) \
    asm volatile("ldmatrix.sync.aligned.m8n8.x4.shared.b16 {%0,%1,%2,%3}, [%4];" \
        : "=r"((r)[0]), "=r"((r)[1]), "=r"((r)[2]), "=r"((r)[3]) \
        : "r"(addr))

__device__ __forceinline__ void mma_bf16(float d[4], const uint32_t a[4],
                                         uint32_t b0, uint32_t b1) {
    asm volatile(
        "mma.sync.aligned.m16n8k16.row.col.f32.bf16.bf16.f32 "
        "{%0,%1,%2,%3}, {%4,%5,%6,%7}, {%8,%9}, {%0,%1,%2,%3};"
        : "+f"(d[0]), "+f"(d[1]), "+f"(d[2]), "+f"(d[3])
        : "r"(a[0]), "r"(a[1]), "r"(a[2]), "r"(a[3]), "r"(b0), "r"(b1));
}

// split (a,b) into bf16 hi pair + bf16 residual pair (packed b32, a low)
__device__ __forceinline__ void pack_split(float a, float b,
                                           uint32_t& hi, uint32_t& lo) {
    __nv_bfloat162 h = __floats2bfloat162_rn(a, b);
    float ra = a - __bfloat162float(h.x);
    float rb = b - __bfloat162float(h.y);
    __nv_bfloat162 l = __floats2bfloat162_rn(ra, rb);
    hi = *reinterpret_cast<uint32_t*>(&h);
    lo = *reinterpret_cast<uint32_t*>(&l);
}

// 16 rows x 64 cols activation fragment, bf16 hi/lo A-frags [ktile][reg]
struct Frag {
    uint32_t h[4][4];
    uint32_t l[4][4];
};

// per-np epilogue for one group: bias + relu (+skip), pack into Aio in place
template <bool HAS_SKIP, bool LAST>
__device__ __forceinline__ void epi_np(
    const float dn[2][4], const float ds[2][4], Frag& Aio, int np,
    const float bv[2][2], const float sv[2][2], int qt,
    float* __restrict__ out0, float* __restrict__ out1)
{
#pragma unroll
    for (int i2 = 0; i2 < 2; ++i2) {
        const int nt = 2 * np + i2;
        float v0 = fmaxf(dn[i2][0] + bv[i2][0], 0.0f);
        float v1 = fmaxf(dn[i2][1] + bv[i2][1], 0.0f);
        float v2 = fmaxf(dn[i2][2] + bv[i2][0], 0.0f);
        float v3 = fmaxf(dn[i2][3] + bv[i2][1], 0.0f);
        if (HAS_SKIP) {
            v0 += fmaxf(ds[i2][0] + sv[i2][0], 0.0f);
            v1 += fmaxf(ds[i2][1] + sv[i2][1], 0.0f);
            v2 += fmaxf(ds[i2][2] + sv[i2][0], 0.0f);
            v3 += fmaxf(ds[i2][3] + sv[i2][1], 0.0f);
        }
        if (LAST) {
            *reinterpret_cast<float2*>(out0 + 8 * nt + 2 * qt) = make_float2(v0, v1);
            *reinterpret_cast<float2*>(out1 + 8 * nt + 2 * qt) = make_float2(v2, v3);
        } else {
            pack_split(v0, v1, Aio.h[np][2 * i2],     Aio.l[np][2 * i2]);
            pack_split(v2, v3, Aio.h[np][2 * i2 + 1], Aio.l[np][2 * i2 + 1]);
        }
    }
}

// One layer for BOTH groups. Ap* = h_{t-1}; Aio* = h_{t-2} on entry (skip
// operand), overwritten with h_t (register dataflow enforces ordering).
template <bool HAS_SKIP, bool LAST>
__device__ __forceinline__ void layer_step(
    const Frag& Ap0, Frag& Aio0, const Frag& Ap1, Frag& Aio1,
    uint32_t wn, uint32_t ws,
    const float* __restrict__ bnp, const float* __restrict__ bsp,
    uint32_t soff0, uint32_t soff1, int qt,
    float* __restrict__ o00, float* __restrict__ o01,
    float* __restrict__ o10, float* __restrict__ o11)
{
    // ---- pass 1: skip GEMM for both groups (deferred accums) ----
    float ds0[4][2][4], ds1[4][2][4];
    if (HAS_SKIP) {
#pragma unroll
        for (int np = 0; np < 4; ++np) {
            uint32_t B[2][8];
#pragma unroll
            for (int i2 = 0; i2 < 2; ++i2) {
                uint32_t s = ws + (uint32_t)(2 * np + i2) * 1024;
                LDSM_X4(&B[i2][0], s + soff0);
                LDSM_X4(&B[i2][4], s + soff1);
            }
#pragma unroll
            for (int i2 = 0; i2 < 2; ++i2)
#pragma unroll
                for (int r = 0; r < 4; ++r) { ds0[np][i2][r] = 0.0f; ds1[np][i2][r] = 0.0f; }
#pragma unroll
            for (int kt = 0; kt < 4; ++kt)
#pragma unroll
                for (int i2 = 0; i2 < 2; ++i2) {
                    mma_bf16(ds0[np][i2], Aio0.h[kt], B[i2][2 * kt], B[i2][2 * kt + 1]);
                    mma_bf16(ds1[np][i2], Aio1.h[kt], B[i2][2 * kt], B[i2][2 * kt + 1]);
                }
#pragma unroll
            for (int kt = 0; kt < 4; ++kt)
#pragma unroll
                for (int i2 = 0; i2 < 2; ++i2) {
                    mma_bf16(ds0[np][i2], Aio0.l[kt], B[i2][2 * kt], B[i2][2 * kt + 1]);
                    mma_bf16(ds1[np][i2], Aio1.l[kt], B[i2][2 * kt], B[i2][2 * kt + 1]);
                }
#pragma unroll
            for (int i2 = 0; i2 < 2; ++i2) {
                uint32_t s = ws + 8192u + (uint32_t)(2 * np + i2) * 1024;
                LDSM_X4(&B[i2][0], s + soff0);
                LDSM_X4(&B[i2][4], s + soff1);
            }
#pragma unroll
            for (int kt = 0; kt < 4; ++kt)
#pragma unroll
                for (int i2 = 0; i2 < 2; ++i2) {
                    mma_bf16(ds0[np][i2], Aio0.h[kt], B[i2][2 * kt], B[i2][2 * kt + 1]);
                    mma_bf16(ds1[np][i2], Aio1.h[kt], B[i2][2 * kt], B[i2][2 * kt + 1]);
                }
        }
    }

    // ---- pass 2: next GEMM per np, both groups, epilogue in place ----
#pragma unroll
    for (int np = 0; np < 4; ++np) {
        uint32_t B[2][8];
#pragma unroll
        for (int i2 = 0; i2 < 2; ++i2) {
            uint32_t a = wn + (uint32_t)(2 * np + i2) * 1024;
            LDSM_X4(&B[i2][0], a + soff0);
            LDSM_X4(&B[i2][4], a + soff1);
        }
        float dn0[2][4], dn1[2][4];
#pragma unroll
        for (int i2 = 0; i2 < 2; ++i2)
#pragma unroll
            for (int r = 0; r < 4; ++r) { dn0[i2][r] = 0.0f; dn1[i2][r] = 0.0f; }
#pragma unroll
        for (int kt = 0; kt < 4; ++kt)
#pragma unroll
            for (int i2 = 0; i2 < 2; ++i2) {
                mma_bf16(dn0[i2], Ap0.h[kt], B[i2][2 * kt], B[i2][2 * kt + 1]);
                mma_bf16(dn1[i2], Ap1.h[kt], B[i2][2 * kt], B[i2][2 * kt + 1]);
            }
#pragma unroll
        for (int kt = 0; kt < 4; ++kt)
#pragma unroll
            for (int i2 = 0; i2 < 2; ++i2) {
                mma_bf16(dn0[i2], Ap0.l[kt], B[i2][2 * kt], B[i2][2 * kt + 1]);
                mma_bf16(dn1[i2], Ap1.l[kt], B[i2][2 * kt], B[i2][2 * kt + 1]);
            }
#pragma unroll
        for (int i2 = 0; i2 < 2; ++i2) {
            uint32_t a = wn + 8192u + (uint32_t)(2 * np + i2) * 1024;
            LDSM_X4(&B[i2][0], a + soff0);
            LDSM_X4(&B[i2][4], a + soff1);
        }
#pragma unroll
        for (int kt = 0; kt < 4; ++kt)
#pragma unroll
            for (int i2 = 0; i2 < 2; ++i2)
                mma_bf16(dn0[i2], Ap0.h[kt], B[i2][2 * kt], B[i2][2 * kt + 1]);

        // biases (shared by both groups)
        float bv[2][2], sv[2][2];
#pragma unroll
        for (int i2 = 0; i2 < 2; ++i2) {
            bv[i2][0] = bnp[8 * (2 * np + i2) + 2 * qt];
            bv[i2][1] = bnp[8 * (2 * np + i2) + 2 * qt + 1];
            if (HAS_SKIP) {
                sv[i2][0] = bsp[8 * (2 * np + i2) + 2 * qt];
                sv[i2][1] = bsp[8 * (2 * np + i2) + 2 * qt + 1];
            }
        }

        // group 0 epilogue first (frees dn0/ds0[np] before g1's 3rd product)
        epi_np<HAS_SKIP, LAST>(dn0, ds0[np], Aio0, np, bv, sv, qt, o00, o01);
#pragma unroll
        for (int kt = 0; kt < 4; ++kt)
#pragma unroll
            for (int i2 = 0; i2 < 2; ++i2)
                mma_bf16(dn1[i2], Ap1.h[kt], B[i2][2 * kt], B[i2][2 * kt + 1]);
        epi_np<HAS_SKIP, LAST>(dn1, ds1[np], Aio1, np, bv, sv, qt, o10, o11);
    }
}

// load 16 rows of x into a Frag (hi/lo)
__device__ __forceinline__ void load_x(const float* __restrict__ xr0,
                                       const float* __restrict__ xr1,
                                       Frag& A, int qt)
{
#pragma unroll
    for (int kt = 0; kt < 4; ++kt) {
        const int c = 16 * kt + 2 * qt;
        float2 p0 = *reinterpret_cast<const float2*>(xr0 + c);
        float2 p1 = *reinterpret_cast<const float2*>(xr1 + c);
        float2 p2 = *reinterpret_cast<const float2*>(xr0 + c + 8);
        float2 p3 = *reinterpret_cast<const float2*>(xr1 + c + 8);
        pack_split(p0.x, p0.y, A.h[kt][0], A.l[kt][0]);
        pack_split(p1.x, p1.y, A.h[kt][1], A.l[kt][1]);
        pack_split(p2.x, p2.y, A.h[kt][2], A.l[kt][2]);
        pack_split(p3.x, p3.y, A.h[kt][3], A.l[kt][3]);
    }
}

__global__ void __launch_bounds__(TPB, 1)
nn_mma_kernel(const float* __restrict__ x,
              const float* __restrict__ Wn_g,
              const float* __restrict__ bn_g,
              const float* __restrict__ Ws_g,
              const float* __restrict__ bs_g,
              float* __restrict__ out)
{
    extern __shared__ unsigned char sm[];
    const uint32_t smb = smem_to_u32(sm);
    const int tid  = threadIdx.x;
    const int wid  = tid >> 5;
    const int lane = tid & 31;
    const int qt   = lane & 3;
    const int grp  = lane >> 2;

    // ---- stage 13 weight matrices as bf16 hi/lo, [n][k] row-major, SW128 ----
    for (int idx = tid; idx < 13 * 4096; idx += TPB) {
        int mat = idx >> 12, e = idx & 4095;
        float v = (mat < 7) ? Wn_g[mat * 4096 + e] : Ws_g[(mat - 7) * 4096 + e];
        __nv_bfloat16 hb = __float2bfloat16(v);
        __nv_bfloat16 lb = __float2bfloat16(v - __bfloat162float(hb));
        int n = e >> 6, k = e & 63;
        uint32_t sw = SMEM_SWIZZLE_128B((uint32_t)(n * 128 + k * 2));
        uint32_t base = OFF_W + (uint32_t)mat * 16384;
        *reinterpret_cast<__nv_bfloat16*>(sm + base + sw)        = hb;
        *reinterpret_cast<__nv_bfloat16*>(sm + base + 8192 + sw) = lb;
    }
    for (int i = tid; i < 448; i += TPB)
        reinterpret_cast<float*>(sm + OFF_BN)[i] = bn_g[i];
    for (int i = tid; i < 384; i += TPB)
        reinterpret_cast<float*>(sm + OFF_BS)[i] = bs_g[i];
    __syncthreads();

    // per-thread ldmatrix.x4 swizzled offsets (k halves 0-31 / 32-63)
    const int r8 = lane & 7, b4 = lane >> 3;
    const uint32_t soff0 = (uint32_t)(r8 * 128 + ((b4 * 16)      ^ (r8 * 16)));
    const uint32_t soff1 = (uint32_t)(r8 * 128 + ((b4 * 16 + 64) ^ (r8 * 16)));

    const float* bn = reinterpret_cast<const float*>(sm + OFF_BN);
    const float* bs = reinterpret_cast<const float*>(sm + OFF_BS);
    const uint32_t w0 = smb + OFF_W;

    // warps independent: global warp-strided loop over 32-row macro-groups
    const int gw = blockIdx.x * (TPB / 32) + wid;

    for (int g = gw; g < NMAC; g += WSTEP) {
        const size_t r00 = (size_t)g * 32 + grp;       // group0 rows
        const size_t r01 = r00 + 8;
        const size_t r10 = r00 + 16;                   // group1 rows
        const size_t r11 = r00 + 24;

        Frag A0g0, A1g0, A0g1, A1g1;
        load_x(x + r00 * 64, x + r01 * 64, A0g0, qt);
        load_x(x + r10 * 64, x + r11 * 64, A0g1, qt);

        float* o00 = out + r00 * 64;
        float* o01 = out + r01 * 64;
        float* o10 = out + r10 * 64;
        float* o11 = out + r11 * 64;

        // layer t: Ap = h_{t-1}, Aio = h_{t-2} -> h_t (slots alternate)
        layer_step<false, false>(A0g0, A1g0, A0g1, A1g1, w0 + 0 * 16384, 0,
                                 bn + 0 * 64, bs, soff0, soff1, qt, o00, o01, o10, o11);
        layer_step<true,  false>(A1g0, A0g0, A1g1, A0g1, w0 + 1 * 16384, w0 + 7 * 16384,
                                 bn + 1 * 64, bs + 0 * 64, soff0, soff1, qt, o00, o01, o10, o11);
        layer_step<true,  false>(A0g0, A1g0, A0g1, A1g1, w0 + 2 * 16384, w0 + 8 * 16384,
                                 bn + 2 * 64, bs + 1 * 64, soff0, soff1, qt, o00, o01, o10, o11);
        layer_step<true,  false>(A1g0, A0g0, A1g1, A0g1, w0 + 3 * 16384, w0 + 9 * 16384,
                                 bn + 3 * 64, bs + 2 * 64, soff0, soff1, qt, o00, o01, o10, o11);
        layer_step<true,  false>(A0g0, A1g0, A0g1, A1g1, w0 + 4 * 16384, w0 + 10 * 16384,
                                 bn + 4 * 64, bs + 3 * 64, soff0, soff1, qt, o00, o01, o10, o11);
        layer_step<true,  false>(A1g0, A0g0, A1g1, A0g1, w0 + 5 * 16384, w0 + 11 * 16384,
                                 bn + 5 * 64, bs + 4 * 64, soff0, soff1, qt, o00, o01, o10, o11);
        layer_step<true,  true >(A0g0, A1g0, A0g1, A1g1, w0 + 6 * 16384, w0 + 12 * 16384,
                                 bn + 6 * 64, bs + 5 * 64, soff0, soff1, qt, o00, o01, o10, o11);
    }
}

extern "C" void kernel_launch(void* const* d_in, const int* in_sizes, int n_in,
                              void* d_out, int out_size)
{
    const float* x  = (const float*)d_in[0];
    const float* Wn = (const float*)d_in[1];
    const float* bn = (const float*)d_in[2];
    const float* Ws = (const float*)d_in[3];
    const float* bs = (const float*)d_in[4];
    float* out = (float*)d_out;

    cudaFuncSetAttribute(nn_mma_kernel,
                         cudaFuncAttributeMaxDynamicSharedMemorySize, SMEM_TOTAL);
    nn_mma_kernel<<<GRID, TPB, SMEM_TOTAL>>>(x, Wn, bn, Ws, bs, out);
}

// round 11
// speedup vs baseline: 1.4595x; 1.4595x over previous
#include <cuda_runtime.h>
#include <cuda_fp16.h>
#include <cstdint>

// NeuralNetwork_28819230556388 — B=262144, D=64, 13 chained 64x64 GEMMs.
// R11: TWO-product fp16 split. A = hiA + loA (fp16 pair, fp32-exact to 2^-22),
// W = single fp16 (quant err 2^-12.8 -> predicted rel_err ~7e-4 < 1e-3).
// MACs x0.67 vs bf16 3-product, W-LDSM x0.5 (one weight kind). Plus
// bias-in-accumulator (D-frags init with bias) and 3-instr relu combine.
// Per-SMSP additive issue model predicts ~155 us (from 225).
// Activations register-resident (2 slots, in-place rotation), weights
// SMEM-resident, persistent CTAs, no barriers in the main loop.

#define TPB     256
#define GRID    148
#define NGROUPS 16384                 // 262144 / 16
#define WSTEP   (GRID * (TPB / 32))   // 1184 warps

// SMEM layout (bytes)
#define OFF_BN 0                      // 7*64 f32 = 1792
#define OFF_BS 1792                   // 6*64 f32 = 1536
#define OFF_W  4096                   // 13 mats * 8192 (single fp16 kind)
#define SMEM_TOTAL (4096 + 13*8192)   // 110592

#define SMEM_SWIZZLE_128B(bo) ((bo) ^ (((bo) >> 3) & 0x70))

__device__ __forceinline__ uint32_t smem_to_u32(const void* p) {
    uint32_t a;
    asm("{ .reg .u64 t; cvta.to.shared.u64 t, %1; cvt.u32.u64 %0, t; }"
        : "=r"(a) : "l"(p));
    return a;
}

#define LDSM_X4(r, addr) \
    asm volatile("ldmatrix.sync.aligned.m8n8.x4.shared.b16 {%0,%1,%2,%3}, [%4];" \
        : "=r"((r)[0]), "=r"((r)[1]), "=r"((r)[2]), "=r"((r)[3]) \
        : "r"(addr))

__device__ __forceinline__ void mma_f16(float d[4], const uint32_t a[4],
                                        uint32_t b0, uint32_t b1) {
    asm volatile(
        "mma.sync.aligned.m16n8k16.row.col.f32.f16.f16.f32 "
        "{%0,%1,%2,%3}, {%4,%5,%6,%7}, {%8,%9}, {%0,%1,%2,%3};"
        : "+f"(d[0]), "+f"(d[1]), "+f"(d[2]), "+f"(d[3])
        : "r"(a[0]), "r"(a[1]), "r"(a[2]), "r"(a[3]), "r"(b0), "r"(b1));
}

// split (a,b) into fp16 hi pair + fp16 residual pair (packed b32, a low)
__device__ __forceinline__ void pack_split(float a, float b,
                                           uint32_t& hi, uint32_t& lo) {
    __half2 h = __floats2half2_rn(a, b);
    float2 f = __half22float2(h);
    __half2 l = __floats2half2_rn(a - f.x, b - f.y);
    hi = *reinterpret_cast<uint32_t*>(&h);
    lo = *reinterpret_cast<uint32_t*>(&l);
}

// 16 rows x 64 cols activation fragment, fp16 hi/lo A-frags [ktile][reg]
struct Frag {
    uint32_t h[4][4];
    uint32_t l[4][4];
};

// One layer. Ap = h_{t-1}. Aio = h_{t-2} on entry (skip operand); pass-2
// epilogue overwrites it with h_t after pass-1 fully consumed it.
// Accumulators are initialized with the bias (relu(acc) = relu(sum + b)).
template <bool HAS_SKIP, bool LAST>
__device__ __forceinline__ void layer_step(
    const Frag& Ap, Frag& Aio,
    uint32_t wn, uint32_t ws,
    const float* __restrict__ bnp, const float* __restrict__ bsp,
    uint32_t soff0, uint32_t soff1, int qt,
    float* __restrict__ out0, float* __restrict__ out1)
{
    // ---- pass 1: skip GEMM, all n-tiles (ds deferred, bias-initialized) ----
    float ds[4][2][4];
    if (HAS_SKIP) {
#pragma unroll
        for (int np = 0; np < 4; ++np) {
            uint32_t B[2][8];
#pragma unroll
            for (int i2 = 0; i2 < 2; ++i2) {
                uint32_t s = ws + (uint32_t)(2 * np + i2) * 1024;
                LDSM_X4(&B[i2][0], s + soff0);
                LDSM_X4(&B[i2][4], s + soff1);
            }
#pragma unroll
            for (int i2 = 0; i2 < 2; ++i2) {
                float s0 = bsp[8 * (2 * np + i2) + 2 * qt];
                float s1 = bsp[8 * (2 * np + i2) + 2 * qt + 1];
                ds[np][i2][0] = s0; ds[np][i2][1] = s1;
                ds[np][i2][2] = s0; ds[np][i2][3] = s1;
            }
#pragma unroll
            for (int kt = 0; kt < 4; ++kt)
#pragma unroll
                for (int i2 = 0; i2 < 2; ++i2)
                    mma_f16(ds[np][i2], Aio.h[kt], B[i2][2 * kt], B[i2][2 * kt + 1]);
#pragma unroll
            for (int kt = 0; kt < 4; ++kt)
#pragma unroll
                for (int i2 = 0; i2 < 2; ++i2)
                    mma_f16(ds[np][i2], Aio.l[kt], B[i2][2 * kt], B[i2][2 * kt + 1]);
        }
    }

    // ---- pass 2: next GEMM per np + epilogue (writes Aio in place) ----
#pragma unroll
    for (int np = 0; np < 4; ++np) {
        uint32_t B[2][8];
#pragma unroll
        for (int i2 = 0; i2 < 2; ++i2) {
            uint32_t a = wn + (uint32_t)(2 * np + i2) * 1024;
            LDSM_X4(&B[i2][0], a + soff0);
            LDSM_X4(&B[i2][4], a + soff1);
        }
        float dn[2][4];
#pragma unroll
        for (int i2 = 0; i2 < 2; ++i2) {
            float b0 = bnp[8 * (2 * np + i2) + 2 * qt];
            float b1 = bnp[8 * (2 * np + i2) + 2 * qt + 1];
            dn[i2][0] = b0; dn[i2][1] = b1; dn[i2][2] = b0; dn[i2][3] = b1;
        }
#pragma unroll
        for (int kt = 0; kt < 4; ++kt)
#pragma unroll
            for (int i2 = 0; i2 < 2; ++i2)
                mma_f16(dn[i2], Ap.h[kt], B[i2][2 * kt], B[i2][2 * kt + 1]);
#pragma unroll
        for (int kt = 0; kt < 4; ++kt)
#pragma unroll
            for (int i2 = 0; i2 < 2; ++i2)
                mma_f16(dn[i2], Ap.l[kt], B[i2][2 * kt], B[i2][2 * kt + 1]);

        // epilogue: v = relu(dn) [+ relu(ds)], pack into Aio in place
#pragma unroll
        for (int i2 = 0; i2 < 2; ++i2) {
            const int nt = 2 * np + i2;
            float v0 = fmaxf(dn[i2][0], 0.0f);
            float v1 = fmaxf(dn[i2][1], 0.0f);
            float v2 = fmaxf(dn[i2][2], 0.0f);
            float v3 = fmaxf(dn[i2][3], 0.0f);
            if (HAS_SKIP) {
                v0 += fmaxf(ds[np][i2][0], 0.0f);
                v1 += fmaxf(ds[np][i2][1], 0.0f);
                v2 += fmaxf(ds[np][i2][2], 0.0f);
                v3 += fmaxf(ds[np][i2][3], 0.0f);
            }
            if (LAST) {
                *reinterpret_cast<float2*>(out0 + 8 * nt + 2 * qt) = make_float2(v0, v1);
                *reinterpret_cast<float2*>(out1 + 8 * nt + 2 * qt) = make_float2(v2, v3);
            } else {
                pack_split(v0, v1, Aio.h[np][2 * i2],     Aio.l[np][2 * i2]);
                pack_split(v2, v3, Aio.h[np][2 * i2 + 1], Aio.l[np][2 * i2 + 1]);
            }
        }
    }
}

__global__ void __launch_bounds__(TPB, 1)
nn_mma_kernel(const float* __restrict__ x,
              const float* __restrict__ Wn_g,
              const float* __restrict__ bn_g,
              const float* __restrict__ Ws_g,
              const float* __restrict__ bs_g,
              float* __restrict__ out)
{
    extern __shared__ unsigned char sm[];
    const uint32_t smb = smem_to_u32(sm);
    const int tid  = threadIdx.x;
    const int wid  = tid >> 5;
    const int lane = tid & 31;
    const int qt   = lane & 3;
    const int grp  = lane >> 2;

    // ---- stage 13 weight matrices as single fp16, [n][k] row-major, SW128 ----
    for (int idx = tid; idx < 13 * 4096; idx += TPB) {
        int mat = idx >> 12, e = idx & 4095;
        float v = (mat < 7) ? Wn_g[mat * 4096 + e] : Ws_g[(mat - 7) * 4096 + e];
        int n = e >> 6, k = e & 63;
        uint32_t sw = SMEM_SWIZZLE_128B((uint32_t)(n * 128 + k * 2));
        *reinterpret_cast<__half*>(sm + OFF_W + mat * 8192 + sw) = __float2half_rn(v);
    }
    for (int i = tid; i < 448; i += TPB)
        reinterpret_cast<float*>(sm + OFF_BN)[i] = bn_g[i];
    for (int i = tid; i < 384; i += TPB)
        reinterpret_cast<float*>(sm + OFF_BS)[i] = bs_g[i];
    __syncthreads();

    // per-thread ldmatrix.x4 swizzled offsets (k halves 0-31 / 32-63)
    const int r8 = lane & 7, b4 = lane >> 3;
    const uint32_t soff0 = (uint32_t)(r8 * 128 + ((b4 * 16)      ^ (r8 * 16)));
    const uint32_t soff1 = (uint32_t)(r8 * 128 + ((b4 * 16 + 64) ^ (r8 * 16)));

    const float* bn = reinterpret_cast<const float*>(sm + OFF_BN);
    const float* bs = reinterpret_cast<const float*>(sm + OFF_BS);
    const uint32_t w0 = smb + OFF_W;

    // warps independent: global warp-strided loop over 16-row groups
    const int gw = blockIdx.x * (TPB / 32) + wid;

    for (int g = gw; g < NGROUPS; g += WSTEP) {
        const size_t gr0 = (size_t)g * 16 + grp;
        const size_t gr1 = gr0 + 8;

        Frag A0, A1;   // two slots; h_t overwrites the slot holding h_{t-2}

        // ---- load x -> A0 (fp16 hi/lo) directly from gmem ----
        {
            const float* xr0 = x + gr0 * 64;
            const float* xr1 = x + gr1 * 64;
#pragma unroll
            for (int kt = 0; kt < 4; ++kt) {
                const int c = 16 * kt + 2 * qt;
                float2 p0 = *reinterpret_cast<const float2*>(xr0 + c);
                float2 p1 = *reinterpret_cast<const float2*>(xr1 + c);
                float2 p2 = *reinterpret_cast<const float2*>(xr0 + c + 8);
                float2 p3 = *reinterpret_cast<const float2*>(xr1 + c + 8);
                pack_split(p0.x, p0.y, A0.h[kt][0], A0.l[kt][0]);
                pack_split(p1.x, p1.y, A0.h[kt][1], A0.l[kt][1]);
                pack_split(p2.x, p2.y, A0.h[kt][2], A0.l[kt][2]);
                pack_split(p3.x, p3.y, A0.h[kt][3], A0.l[kt][3]);
            }
        }

        float* o0 = out + gr0 * 64;
        float* o1 = out + gr1 * 64;

        // layer t: Ap = h_{t-1}, Aio = h_{t-2} -> h_t
        layer_step<false, false>(A0, A1, w0 + 0 * 8192, 0,
                                 bn + 0 * 64, bs, soff0, soff1, qt, o0, o1);           // h1 -> A1
        layer_step<true,  false>(A1, A0, w0 + 1 * 8192, w0 + 7 * 8192,
                                 bn + 1 * 64, bs + 0 * 64, soff0, soff1, qt, o0, o1);  // h2 -> A0
        layer_step<true,  false>(A0, A1, w0 + 2 * 8192, w0 + 8 * 8192,
                                 bn + 2 * 64, bs + 1 * 64, soff0, soff1, qt, o0, o1);  // h3 -> A1
        layer_step<true,  false>(A1, A0, w0 + 3 * 8192, w0 + 9 * 8192,
                                 bn + 3 * 64, bs + 2 * 64, soff0, soff1, qt, o0, o1);  // h4 -> A0
        layer_step<true,  false>(A0, A1, w0 + 4 * 8192, w0 + 10 * 8192,
                                 bn + 4 * 64, bs + 3 * 64, soff0, soff1, qt, o0, o1);  // h5 -> A1
        layer_step<true,  false>(A1, A0, w0 + 5 * 8192, w0 + 11 * 8192,
                                 bn + 5 * 64, bs + 4 * 64, soff0, soff1, qt, o0, o1);  // h6 -> A0
        layer_step<true,  true >(A0, A1, w0 + 6 * 8192, w0 + 12 * 8192,
                                 bn + 6 * 64, bs + 5 * 64, soff0, soff1, qt, o0, o1);  // h7 -> out
    }
}

extern "C" void kernel_launch(void* const* d_in, const int* in_sizes, int n_in,
                              void* d_out, int out_size)
{
    const float* x  = (const float*)d_in[0];
    const float* Wn = (const float*)d_in[1];
    const float* bn = (const float*)d_in[2];
    const float* Ws = (const float*)d_in[3];
    const float* bs = (const float*)d_in[4];
    float* out = (float*)d_out;

    cudaFuncSetAttribute(nn_mma_kernel,
                         cudaFuncAttributeMaxDynamicSharedMemorySize, SMEM_TOTAL);
    nn_mma_kernel<<<GRID, TPB, SMEM_TOTAL>>>(x, Wn, bn, Ws, bs, out);
}

// round 12
// speedup vs baseline: 2.0000x; 1.3703x over previous
#include <cuda_runtime.h>
#include <cuda_fp16.h>
#include <cstdint>

// NeuralNetwork_28819230556388 — B=262144, D=64, 13 chained 64x64 GEMMs.
// R12: pure fp16 network (single product): A and W both fp16, fp32 accumulate.
// Error model (calibrated on R11 measurement: 0.34x naive accumulation):
// per-layer eps ~3.1e-4, total ~4-5e-4 < 1e-3. MACs x0.5 vs R11.
// Bias-in-accumulator, relu-combine epilogue, activations register-resident
// (2 slots, in-place rotation), weights SMEM-resident, persistent CTAs,
// no barriers in the main loop.

#define TPB     256
#define GRID    148
#define NGROUPS 16384                 // 262144 / 16
#define WSTEP   (GRID * (TPB / 32))   // 1184 warps

// SMEM layout (bytes)
#define OFF_BN 0                      // 7*64 f32 = 1792
#define OFF_BS 1792                   // 6*64 f32 = 1536
#define OFF_W  4096                   // 13 mats * 8192 fp16
#define SMEM_TOTAL (4096 + 13*8192)   // 110592

#define SMEM_SWIZZLE_128B(bo) ((bo) ^ (((bo) >> 3) & 0x70))

__device__ __forceinline__ uint32_t smem_to_u32(const void* p) {
    uint32_t a;
    asm("{ .reg .u64 t; cvta.to.shared.u64 t, %1; cvt.u32.u64 %0, t; }"
        : "=r"(a) : "l"(p));
    return a;
}

#define LDSM_X4(r, addr) \
    asm volatile("ldmatrix.sync.aligned.m8n8.x4.shared.b16 {%0,%1,%2,%3}, [%4];" \
        : "=r"((r)[0]), "=r"((r)[1]), "=r"((r)[2]), "=r"((r)[3]) \
        : "r"(addr))

__device__ __forceinline__ void mma_f16(float d[4], const uint32_t a[4],
                                        uint32_t b0, uint32_t b1) {
    asm volatile(
        "mma.sync.aligned.m16n8k16.row.col.f32.f16.f16.f32 "
        "{%0,%1,%2,%3}, {%4,%5,%6,%7}, {%8,%9}, {%0,%1,%2,%3};"
        : "+f"(d[0]), "+f"(d[1]), "+f"(d[2]), "+f"(d[3])
        : "r"(a[0]), "r"(a[1]), "r"(a[2]), "r"(a[3]), "r"(b0), "r"(b1));
}

__device__ __forceinline__ uint32_t pk_h2(float a, float b) {
    __half2 h = __floats2half2_rn(a, b);
    return *reinterpret_cast<uint32_t*>(&h);
}

// 16 rows x 64 cols activation fragment, fp16 A-frags [ktile][reg]
struct Frag {
    uint32_t a[4][4];
};

// One layer. Ap = h_{t-1}. Aio = h_{t-2} on entry (skip operand); pass-2
// epilogue overwrites it with h_t after pass-1 fully consumed it.
// Accumulators initialized with bias (relu(acc) = relu(sum + b)).
template <bool HAS_SKIP, bool LAST>
__device__ __forceinline__ void layer_step(
    const Frag& Ap, Frag& Aio,
    uint32_t wn, uint32_t ws,
    const float* __restrict__ bnp, const float* __restrict__ bsp,
    uint32_t soff0, uint32_t soff1, int qt,
    float* __restrict__ out0, float* __restrict__ out1)
{
    // ---- pass 1: skip GEMM, all n-tiles (ds deferred, bias-initialized) ----
    float ds[4][2][4];
    if (HAS_SKIP) {
#pragma unroll
        for (int np = 0; np < 4; ++np) {
            uint32_t B[2][8];
#pragma unroll
            for (int i2 = 0; i2 < 2; ++i2) {
                uint32_t s = ws + (uint32_t)(2 * np + i2) * 1024;
                LDSM_X4(&B[i2][0], s + soff0);
                LDSM_X4(&B[i2][4], s + soff1);
            }
#pragma unroll
            for (int i2 = 0; i2 < 2; ++i2) {
                float s0 = bsp[8 * (2 * np + i2) + 2 * qt];
                float s1 = bsp[8 * (2 * np + i2) + 2 * qt + 1];
                ds[np][i2][0] = s0; ds[np][i2][1] = s1;
                ds[np][i2][2] = s0; ds[np][i2][3] = s1;
            }
#pragma unroll
            for (int kt = 0; kt < 4; ++kt)
#pragma unroll
                for (int i2 = 0; i2 < 2; ++i2)
                    mma_f16(ds[np][i2], Aio.a[kt], B[i2][2 * kt], B[i2][2 * kt + 1]);
        }
    }

    // ---- pass 2: next GEMM per np + epilogue (writes Aio in place) ----
#pragma unroll
    for (int np = 0; np < 4; ++np) {
        uint32_t B[2][8];
#pragma unroll
        for (int i2 = 0; i2 < 2; ++i2) {
            uint32_t a = wn + (uint32_t)(2 * np + i2) * 1024;
            LDSM_X4(&B[i2][0], a + soff0);
            LDSM_X4(&B[i2][4], a + soff1);
        }
        float dn[2][4];
#pragma unroll
        for (int i2 = 0; i2 < 2; ++i2) {
            float b0 = bnp[8 * (2 * np + i2) + 2 * qt];
            float b1 = bnp[8 * (2 * np + i2) + 2 * qt + 1];
            dn[i2][0] = b0; dn[i2][1] = b1; dn[i2][2] = b0; dn[i2][3] = b1;
        }
#pragma unroll
        for (int kt = 0; kt < 4; ++kt)
#pragma unroll
            for (int i2 = 0; i2 < 2; ++i2)
                mma_f16(dn[i2], Ap.a[kt], B[i2][2 * kt], B[i2][2 * kt + 1]);

        // epilogue: v = relu(dn) [+ relu(ds)], pack fp16 into Aio in place
#pragma unroll
        for (int i2 = 0; i2 < 2; ++i2) {
            const int nt = 2 * np + i2;
            float v0 = fmaxf(dn[i2][0], 0.0f);
            float v1 = fmaxf(dn[i2][1], 0.0f);
            float v2 = fmaxf(dn[i2][2], 0.0f);
            float v3 = fmaxf(dn[i2][3], 0.0f);
            if (HAS_SKIP) {
                v0 += fmaxf(ds[np][i2][0], 0.0f);
                v1 += fmaxf(ds[np][i2][1], 0.0f);
                v2 += fmaxf(ds[np][i2][2], 0.0f);
                v3 += fmaxf(ds[np][i2][3], 0.0f);
            }
            if (LAST) {
                *reinterpret_cast<float2*>(out0 + 8 * nt + 2 * qt) = make_float2(v0, v1);
                *reinterpret_cast<float2*>(out1 + 8 * nt + 2 * qt) = make_float2(v2, v3);
            } else {
                Aio.a[np][2 * i2]     = pk_h2(v0, v1);
                Aio.a[np][2 * i2 + 1] = pk_h2(v2, v3);
            }
        }
    }
}

__global__ void __launch_bounds__(TPB, 1)
nn_mma_kernel(const float* __restrict__ x,
              const float* __restrict__ Wn_g,
              const float* __restrict__ bn_g,
              const float* __restrict__ Ws_g,
              const float* __restrict__ bs_g,
              float* __restrict__ out)
{
    extern __shared__ unsigned char sm[];
    const uint32_t smb = smem_to_u32(sm);
    const int tid  = threadIdx.x;
    const int wid  = tid >> 5;
    const int lane = tid & 31;
    const int qt   = lane & 3;
    const int grp  = lane >> 2;

    // ---- stage 13 weight matrices as fp16, [n][k] row-major, SW128 ----
    for (int idx = tid; idx < 13 * 4096; idx += TPB) {
        int mat = idx >> 12, e = idx & 4095;
        float v = (mat < 7) ? Wn_g[mat * 4096 + e] : Ws_g[(mat - 7) * 4096 + e];
        int n = e >> 6, k = e & 63;
        uint32_t sw = SMEM_SWIZZLE_128B((uint32_t)(n * 128 + k * 2));
        *reinterpret_cast<__half*>(sm + OFF_W + mat * 8192 + sw) = __float2half_rn(v);
    }
    for (int i = tid; i < 448; i += TPB)
        reinterpret_cast<float*>(sm + OFF_BN)[i] = bn_g[i];
    for (int i = tid; i < 384; i += TPB)
        reinterpret_cast<float*>(sm + OFF_BS)[i] = bs_g[i];
    __syncthreads();

    // per-thread ldmatrix.x4 swizzled offsets (k halves 0-31 / 32-63)
    const int r8 = lane & 7, b4 = lane >> 3;
    const uint32_t soff0 = (uint32_t)(r8 * 128 + ((b4 * 16)      ^ (r8 * 16)));
    const uint32_t soff1 = (uint32_t)(r8 * 128 + ((b4 * 16 + 64) ^ (r8 * 16)));

    const float* bn = reinterpret_cast<const float*>(sm + OFF_BN);
    const float* bs = reinterpret_cast<const float*>(sm + OFF_BS);
    const uint32_t w0 = smb + OFF_W;

    // warps independent: global warp-strided loop over 16-row groups
    const int gw = blockIdx.x * (TPB / 32) + wid;

    for (int g = gw; g < NGROUPS; g += WSTEP) {
        const size_t gr0 = (size_t)g * 16 + grp;
        const size_t gr1 = gr0 + 8;

        Frag A0, A1;   // two slots; h_t overwrites the slot holding h_{t-2}

        // ---- load x -> A0 (fp16) directly from gmem ----
        {
            const float* xr0 = x + gr0 * 64;
            const float* xr1 = x + gr1 * 64;
#pragma unroll
            for (int kt = 0; kt < 4; ++kt) {
                const int c = 16 * kt + 2 * qt;
                float2 p0 = *reinterpret_cast<const float2*>(xr0 + c);
                float2 p1 = *reinterpret_cast<const float2*>(xr1 + c);
                float2 p2 = *reinterpret_cast<const float2*>(xr0 + c + 8);
                float2 p3 = *reinterpret_cast<const float2*>(xr1 + c + 8);
                A0.a[kt][0] = pk_h2(p0.x, p0.y);
                A0.a[kt][1] = pk_h2(p1.x, p1.y);
                A0.a[kt][2] = pk_h2(p2.x, p2.y);
                A0.a[kt][3] = pk_h2(p3.x, p3.y);
            }
        }

        float* o0 = out + gr0 * 64;
        float* o1 = out + gr1 * 64;

        // layer t: Ap = h_{t-1}, Aio = h_{t-2} -> h_t
        layer_step<false, false>(A0, A1, w0 + 0 * 8192, 0,
                                 bn + 0 * 64, bs, soff0, soff1, qt, o0, o1);           // h1 -> A1
        layer_step<true,  false>(A1, A0, w0 + 1 * 8192, w0 + 7 * 8192,
                                 bn + 1 * 64, bs + 0 * 64, soff0, soff1, qt, o0, o1);  // h2 -> A0
        layer_step<true,  false>(A0, A1, w0 + 2 * 8192, w0 + 8 * 8192,
                                 bn + 2 * 64, bs + 1 * 64, soff0, soff1, qt, o0, o1);  // h3 -> A1
        layer_step<true,  false>(A1, A0, w0 + 3 * 8192, w0 + 9 * 8192,
                                 bn + 3 * 64, bs + 2 * 64, soff0, soff1, qt, o0, o1);  // h4 -> A0
        layer_step<true,  false>(A0, A1, w0 + 4 * 8192, w0 + 10 * 8192,
                                 bn + 4 * 64, bs + 3 * 64, soff0, soff1, qt, o0, o1);  // h5 -> A1
        layer_step<true,  false>(A1, A0, w0 + 5 * 8192, w0 + 11 * 8192,
                                 bn + 5 * 64, bs + 4 * 64, soff0, soff1, qt, o0, o1);  // h6 -> A0
        layer_step<true,  true >(A0, A1, w0 + 6 * 8192, w0 + 12 * 8192,
                                 bn + 6 * 64, bs + 5 * 64, soff0, soff1, qt, o0, o1);  // h7 -> out
    }
}

extern "C" void kernel_launch(void* const* d_in, const int* in_sizes, int n_in,
                              void* d_out, int out_size)
{
    const float* x  = (const float*)d_in[0];
    const float* Wn = (const float*)d_in[1];
    const float* bn = (const float*)d_in[2];
    const float* Ws = (const float*)d_in[3];
    const float* bs = (const float*)d_in[4];
    float* out = (float*)d_out;

    cudaFuncSetAttribute(nn_mma_kernel,
                         cudaFuncAttributeMaxDynamicSharedMemorySize, SMEM_TOTAL);
    nn_mma_kernel<<<GRID, TPB, SMEM_TOTAL>>>(x, Wn, bn, Ws, bs, out);
}

// round 13
// speedup vs baseline: 2.0742x; 1.0371x over previous
#include <cuda_runtime.h>
#include <cuda_fp16.h>
#include <cstdint>

// NeuralNetwork_28819230556388 — B=262144, D=64, 13 chained 64x64 GEMMs.
// R13: pure fp16 single-product (R12 arithmetic, rel_err 3.67e-4) with TWO
// 16-row groups per warp sharing every ldmatrix'd B-fragment (LDSM + bias
// loads + loop overhead per row halved; GEMM bursts doubled). Fits in ~206
// regs now that frags are fp16-only (R10's version of this spilled at 255).
// Bias-in-accumulator, relu-combine epilogue, activations register-resident
// (2 slots per group, in-place rotation), weights SMEM-resident, persistent
// CTAs, no barriers in the main loop.

#define TPB     256
#define GRID    148
#define NMAC    8192                  // 262144 / 32 rows per macro-group
#define WSTEP   (GRID * (TPB / 32))   // 1184 warps

// SMEM layout (bytes)
#define OFF_BN 0                      // 7*64 f32 = 1792
#define OFF_BS 1792                   // 6*64 f32 = 1536
#define OFF_W  4096                   // 13 mats * 8192 fp16
#define SMEM_TOTAL (4096 + 13*8192)   // 110592

#define SMEM_SWIZZLE_128B(bo) ((bo) ^ (((bo) >> 3) & 0x70))

__device__ __forceinline__ uint32_t smem_to_u32(const void* p) {
    uint32_t a;
    asm("{ .reg .u64 t; cvta.to.shared.u64 t, %1; cvt.u32.u64 %0, t; }"
        : "=r"(a) : "l"(p));
    return a;
}

#define LDSM_X4(r, addr) \
    asm volatile("ldmatrix.sync.aligned.m8n8.x4.shared.b16 {%0,%1,%2,%3}, [%4];" \
        : "=r"((r)[0]), "=r"((r)[1]), "=r"((r)[2]), "=r"((r)[3]) \
        : "r"(addr))

__device__ __forceinline__ void mma_f16(float d[4], const uint32_t a[4],
                                        uint32_t b0, uint32_t b1) {
    asm volatile(
        "mma.sync.aligned.m16n8k16.row.col.f32.f16.f16.f32 "
        "{%0,%1,%2,%3}, {%4,%5,%6,%7}, {%8,%9}, {%0,%1,%2,%3};"
        : "+f"(d[0]), "+f"(d[1]), "+f"(d[2]), "+f"(d[3])
        : "r"(a[0]), "r"(a[1]), "r"(a[2]), "r"(a[3]), "r"(b0), "r"(b1));
}

__device__ __forceinline__ uint32_t pk_h2(float a, float b) {
    __half2 h = __floats2half2_rn(a, b);
    return *reinterpret_cast<uint32_t*>(&h);
}

// 16 rows x 64 cols activation fragment, fp16 A-frags [ktile][reg]
struct Frag {
    uint32_t a[4][4];
};

// per-np epilogue for one group: v = relu(dn) [+ relu(ds)], pack in place
template <bool HAS_SKIP, bool LAST>
__device__ __forceinline__ void epi_np(
    const float dn[2][4], const float ds[2][4], Frag& Aio, int np, int qt,
    float* __restrict__ out0, float* __restrict__ out1)
{
#pragma unroll
    for (int i2 = 0; i2 < 2; ++i2) {
        const int nt = 2 * np + i2;
        float v0 = fmaxf(dn[i2][0], 0.0f);
        float v1 = fmaxf(dn[i2][1], 0.0f);
        float v2 = fmaxf(dn[i2][2], 0.0f);
        float v3 = fmaxf(dn[i2][3], 0.0f);
        if (HAS_SKIP) {
            v0 += fmaxf(ds[i2][0], 0.0f);
            v1 += fmaxf(ds[i2][1], 0.0f);
            v2 += fmaxf(ds[i2][2], 0.0f);
            v3 += fmaxf(ds[i2][3], 0.0f);
        }
        if (LAST) {
            *reinterpret_cast<float2*>(out0 + 8 * nt + 2 * qt) = make_float2(v0, v1);
            *reinterpret_cast<float2*>(out1 + 8 * nt + 2 * qt) = make_float2(v2, v3);
        } else {
            Aio.a[np][2 * i2]     = pk_h2(v0, v1);
            Aio.a[np][2 * i2 + 1] = pk_h2(v2, v3);
        }
    }
}

// One layer for BOTH groups. Ap* = h_{t-1}; Aio* = h_{t-2} on entry (skip
// operand), overwritten with h_t (register dataflow enforces ordering).
// Accumulators initialized with bias.
template <bool HAS_SKIP, bool LAST>
__device__ __forceinline__ void layer_step(
    const Frag& Ap0, Frag& Aio0, const Frag& Ap1, Frag& Aio1,
    uint32_t wn, uint32_t ws,
    const float* __restrict__ bnp, const float* __restrict__ bsp,
    uint32_t soff0, uint32_t soff1, int qt,
    float* __restrict__ o00, float* __restrict__ o01,
    float* __restrict__ o10, float* __restrict__ o11)
{
    // ---- pass 1: skip GEMM for both groups (ds deferred, bias-init) ----
    float ds0[4][2][4], ds1[4][2][4];
    if (HAS_SKIP) {
#pragma unroll
        for (int np = 0; np < 4; ++np) {
            uint32_t B[2][8];
#pragma unroll
            for (int i2 = 0; i2 < 2; ++i2) {
                uint32_t s = ws + (uint32_t)(2 * np + i2) * 1024;
                LDSM_X4(&B[i2][0], s + soff0);
                LDSM_X4(&B[i2][4], s + soff1);
            }
#pragma unroll
            for (int i2 = 0; i2 < 2; ++i2) {
                float s0 = bsp[8 * (2 * np + i2) + 2 * qt];
                float s1 = bsp[8 * (2 * np + i2) + 2 * qt + 1];
                ds0[np][i2][0] = s0; ds0[np][i2][1] = s1;
                ds0[np][i2][2] = s0; ds0[np][i2][3] = s1;
                ds1[np][i2][0] = s0; ds1[np][i2][1] = s1;
                ds1[np][i2][2] = s0; ds1[np][i2][3] = s1;
            }
#pragma unroll
            for (int kt = 0; kt < 4; ++kt)
#pragma unroll
                for (int i2 = 0; i2 < 2; ++i2) {
                    mma_f16(ds0[np][i2], Aio0.a[kt], B[i2][2 * kt], B[i2][2 * kt + 1]);
                    mma_f16(ds1[np][i2], Aio1.a[kt], B[i2][2 * kt], B[i2][2 * kt + 1]);
                }
        }
    }

    // ---- pass 2: next GEMM per np, both groups, epilogue in place ----
#pragma unroll
    for (int np = 0; np < 4; ++np) {
        uint32_t B[2][8];
#pragma unroll
        for (int i2 = 0; i2 < 2; ++i2) {
            uint32_t a = wn + (uint32_t)(2 * np + i2) * 1024;
            LDSM_X4(&B[i2][0], a + soff0);
            LDSM_X4(&B[i2][4], a + soff1);
        }
        float dn0[2][4], dn1[2][4];
#pragma unroll
        for (int i2 = 0; i2 < 2; ++i2) {
            float b0 = bnp[8 * (2 * np + i2) + 2 * qt];
            float b1 = bnp[8 * (2 * np + i2) + 2 * qt + 1];
            dn0[i2][0] = b0; dn0[i2][1] = b1; dn0[i2][2] = b0; dn0[i2][3] = b1;
            dn1[i2][0] = b0; dn1[i2][1] = b1; dn1[i2][2] = b0; dn1[i2][3] = b1;
        }
#pragma unroll
        for (int kt = 0; kt < 4; ++kt)
#pragma unroll
            for (int i2 = 0; i2 < 2; ++i2) {
                mma_f16(dn0[i2], Ap0.a[kt], B[i2][2 * kt], B[i2][2 * kt + 1]);
                mma_f16(dn1[i2], Ap1.a[kt], B[i2][2 * kt], B[i2][2 * kt + 1]);
            }
        epi_np<HAS_SKIP, LAST>(dn0, ds0[np], Aio0, np, qt, o00, o01);
        epi_np<HAS_SKIP, LAST>(dn1, ds1[np], Aio1, np, qt, o10, o11);
    }
}

// load 16 rows of x into a Frag (fp16)
__device__ __forceinline__ void load_x(const float* __restrict__ xr0,
                                       const float* __restrict__ xr1,
                                       Frag& A, int qt)
{
#pragma unroll
    for (int kt = 0; kt < 4; ++kt) {
        const int c = 16 * kt + 2 * qt;
        float2 p0 = *reinterpret_cast<const float2*>(xr0 + c);
        float2 p1 = *reinterpret_cast<const float2*>(xr1 + c);
        float2 p2 = *reinterpret_cast<const float2*>(xr0 + c + 8);
        float2 p3 = *reinterpret_cast<const float2*>(xr1 + c + 8);
        A.a[kt][0] = pk_h2(p0.x, p0.y);
        A.a[kt][1] = pk_h2(p1.x, p1.y);
        A.a[kt][2] = pk_h2(p2.x, p2.y);
        A.a[kt][3] = pk_h2(p3.x, p3.y);
    }
}

__global__ void __launch_bounds__(TPB, 1)
nn_mma_kernel(const float* __restrict__ x,
              const float* __restrict__ Wn_g,
              const float* __restrict__ bn_g,
              const float* __restrict__ Ws_g,
              const float* __restrict__ bs_g,
              float* __restrict__ out)
{
    extern __shared__ unsigned char sm[];
    const uint32_t smb = smem_to_u32(sm);
    const int tid  = threadIdx.x;
    const int wid  = tid >> 5;
    const int lane = tid & 31;
    const int qt   = lane & 3;
    const int grp  = lane >> 2;

    // ---- stage 13 weight matrices as fp16, [n][k] row-major, SW128 ----
    for (int idx = tid; idx < 13 * 4096; idx += TPB) {
        int mat = idx >> 12, e = idx & 4095;
        float v = (mat < 7) ? Wn_g[mat * 4096 + e] : Ws_g[(mat - 7) * 4096 + e];
        int n = e >> 6, k = e & 63;
        uint32_t sw = SMEM_SWIZZLE_128B((uint32_t)(n * 128 + k * 2));
        *reinterpret_cast<__half*>(sm + OFF_W + mat * 8192 + sw) = __float2half_rn(v);
    }
    for (int i = tid; i < 448; i += TPB)
        reinterpret_cast<float*>(sm + OFF_BN)[i] = bn_g[i];
    for (int i = tid; i < 384; i += TPB)
        reinterpret_cast<float*>(sm + OFF_BS)[i] = bs_g[i];
    __syncthreads();

    // per-thread ldmatrix.x4 swizzled offsets (k halves 0-31 / 32-63)
    const int r8 = lane & 7, b4 = lane >> 3;
    const uint32_t soff0 = (uint32_t)(r8 * 128 + ((b4 * 16)      ^ (r8 * 16)));
    const uint32_t soff1 = (uint32_t)(r8 * 128 + ((b4 * 16 + 64) ^ (r8 * 16)));

    const float* bn = reinterpret_cast<const float*>(sm + OFF_BN);
    const float* bs = reinterpret_cast<const float*>(sm + OFF_BS);
    const uint32_t w0 = smb + OFF_W;

    // warps independent: global warp-strided loop over 32-row macro-groups
    const int gw = blockIdx.x * (TPB / 32) + wid;

    for (int g = gw; g < NMAC; g += WSTEP) {
        const size_t r00 = (size_t)g * 32 + grp;       // group0 rows
        const size_t r01 = r00 + 8;
        const size_t r10 = r00 + 16;                   // group1 rows
        const size_t r11 = r00 + 24;

        Frag A0g0, A1g0, A0g1, A1g1;
        load_x(x + r00 * 64, x + r01 * 64, A0g0, qt);
        load_x(x + r10 * 64, x + r11 * 64, A0g1, qt);

        float* o00 = out + r00 * 64;
        float* o01 = out + r01 * 64;
        float* o10 = out + r10 * 64;
        float* o11 = out + r11 * 64;

        // layer t: Ap = h_{t-1}, Aio = h_{t-2} -> h_t (slots alternate)
        layer_step<false, false>(A0g0, A1g0, A0g1, A1g1, w0 + 0 * 8192, 0,
                                 bn + 0 * 64, bs, soff0, soff1, qt, o00, o01, o10, o11);
        layer_step<true,  false>(A1g0, A0g0, A1g1, A0g1, w0 + 1 * 8192, w0 + 7 * 8192,
                                 bn + 1 * 64, bs + 0 * 64, soff0, soff1, qt, o00, o01, o10, o11);
        layer_step<true,  false>(A0g0, A1g0, A0g1, A1g1, w0 + 2 * 8192, w0 + 8 * 8192,
                                 bn + 2 * 64, bs + 1 * 64, soff0, soff1, qt, o00, o01, o10, o11);
        layer_step<true,  false>(A1g0, A0g0, A1g1, A0g1, w0 + 3 * 8192, w0 + 9 * 8192,
                                 bn + 3 * 64, bs + 2 * 64, soff0, soff1, qt, o00, o01, o10, o11);
        layer_step<true,  false>(A0g0, A1g0, A0g1, A1g1, w0 + 4 * 8192, w0 + 10 * 8192,
                                 bn + 4 * 64, bs + 3 * 64, soff0, soff1, qt, o00, o01, o10, o11);
        layer_step<true,  false>(A1g0, A0g0, A1g1, A0g1, w0 + 5 * 8192, w0 + 11 * 8192,
                                 bn + 5 * 64, bs + 4 * 64, soff0, soff1, qt, o00, o01, o10, o11);
        layer_step<true,  true >(A0g0, A1g0, A0g1, A1g1, w0 + 6 * 8192, w0 + 12 * 8192,
                                 bn + 6 * 64, bs + 5 * 64, soff0, soff1, qt, o00, o01, o10, o11);
    }
}

extern "C" void kernel_launch(void* const* d_in, const int* in_sizes, int n_in,
                              void* d_out, int out_size)
{
    const float* x  = (const float*)d_in[0];
    const float* Wn = (const float*)d_in[1];
    const float* bn = (const float*)d_in[2];
    const float* Ws = (const float*)d_in[3];
    const float* bs = (const float*)d_in[4];
    float* out = (float*)d_out;

    cudaFuncSetAttribute(nn_mma_kernel,
                         cudaFuncAttributeMaxDynamicSharedMemorySize, SMEM_TOTAL);
    nn_mma_kernel<<<GRID, TPB, SMEM_TOTAL>>>(x, Wn, bn, Ws, bs, out);
}

// round 14
// speedup vs baseline: 2.1318x; 1.0278x over previous
#include <cuda_runtime.h>
#include <cuda_fp16.h>
#include <cstdint>

// NeuralNetwork_28819230556388 — B=262144, D=64, 13 chained 64x64 GEMMs.
// R14: fp16 single-product, 2 groups/warp with shared B-frags, now with
//  (a) THREE activation slots per group (h_t -> S[t%3]): the written slot is
//      h_{t-3} (dead), so next+skip+epilogue fuse per n-tile and skip
//      accumulators are transient (32 regs) instead of layer-live (64) —
//      R13 hit regs=255 from that live range; this targets ~216.
//  (b) half2 epilogue: relu/skip-add via __hmax2/__hadd2 on packed halves
//      (14 -> 10 instrs per 8 outputs). One extra fp16 rounding per branch:
//      predicted rel_err ~5e-4 (from 3.67e-4), still < 1e-3. LAST layer
//      keeps exact fp32 epilogue.
// Bias-in-accumulator, weights SMEM-resident, persistent CTAs, no barriers.

#define TPB     256
#define GRID    148
#define NMAC    8192                  // 262144 / 32 rows per macro-group
#define WSTEP   (GRID * (TPB / 32))   // 1184 warps

// SMEM layout (bytes)
#define OFF_BN 0                      // 7*64 f32 = 1792
#define OFF_BS 1792                   // 6*64 f32 = 1536
#define OFF_W  4096                   // 13 mats * 8192 fp16
#define SMEM_TOTAL (4096 + 13*8192)   // 110592

#define SMEM_SWIZZLE_128B(bo) ((bo) ^ (((bo) >> 3) & 0x70))

__device__ __forceinline__ uint32_t smem_to_u32(const void* p) {
    uint32_t a;
    asm("{ .reg .u64 t; cvta.to.shared.u64 t, %1; cvt.u32.u64 %0, t; }"
        : "=r"(a) : "l"(p));
    return a;
}

#define LDSM_X4(r, addr) \
    asm volatile("ldmatrix.sync.aligned.m8n8.x4.shared.b16 {%0,%1,%2,%3}, [%4];" \
        : "=r"((r)[0]), "=r"((r)[1]), "=r"((r)[2]), "=r"((r)[3]) \
        : "r"(addr))

__device__ __forceinline__ void mma_f16(float d[4], const uint32_t a[4],
                                        uint32_t b0, uint32_t b1) {
    asm volatile(
        "mma.sync.aligned.m16n8k16.row.col.f32.f16.f16.f32 "
        "{%0,%1,%2,%3}, {%4,%5,%6,%7}, {%8,%9}, {%0,%1,%2,%3};"
        : "+f"(d[0]), "+f"(d[1]), "+f"(d[2]), "+f"(d[3])
        : "r"(a[0]), "r"(a[1]), "r"(a[2]), "r"(a[3]), "r"(b0), "r"(b1));
}

__device__ __forceinline__ uint32_t pk_h2(float a, float b) {
    __half2 h = __floats2half2_rn(a, b);
    return *reinterpret_cast<uint32_t*>(&h);
}

// 16 rows x 64 cols activation fragment, fp16 A-frags [ktile][reg]
struct Frag {
    uint32_t a[4][4];
};

// half2 epilogue for one group's np: An = hmax2(dn,0) [+ hmax2(ds,0)]
template <bool HAS_SKIP>
__device__ __forceinline__ void epi_h2(const float dn[2][4], const float ds[2][4],
                                       Frag& An, int np)
{
    const __half2 z = __float2half2_rn(0.0f);
#pragma unroll
    for (int i2 = 0; i2 < 2; ++i2) {
        __half2 n01 = __floats2half2_rn(dn[i2][0], dn[i2][1]);
        __half2 n23 = __floats2half2_rn(dn[i2][2], dn[i2][3]);
        n01 = __hmax2(n01, z);
        n23 = __hmax2(n23, z);
        if (HAS_SKIP) {
            __half2 s01 = __floats2half2_rn(ds[i2][0], ds[i2][1]);
            __half2 s23 = __floats2half2_rn(ds[i2][2], ds[i2][3]);
            n01 = __hadd2(n01, __hmax2(s01, z));
            n23 = __hadd2(n23, __hmax2(s23, z));
        }
        An.a[np][2 * i2]     = *reinterpret_cast<uint32_t*>(&n01);
        An.a[np][2 * i2 + 1] = *reinterpret_cast<uint32_t*>(&n23);
    }
}

// exact fp32 epilogue for the final layer (writes gmem)
template <bool HAS_SKIP>
__device__ __forceinline__ void epi_last(const float dn[2][4], const float ds[2][4],
                                         int np, int qt,
                                         float* __restrict__ out0,
                                         float* __restrict__ out1)
{
#pragma unroll
    for (int i2 = 0; i2 < 2; ++i2) {
        const int nt = 2 * np + i2;
        float v0 = fmaxf(dn[i2][0], 0.0f);
        float v1 = fmaxf(dn[i2][1], 0.0f);
        float v2 = fmaxf(dn[i2][2], 0.0f);
        float v3 = fmaxf(dn[i2][3], 0.0f);
        if (HAS_SKIP) {
            v0 += fmaxf(ds[i2][0], 0.0f);
            v1 += fmaxf(ds[i2][1], 0.0f);
            v2 += fmaxf(ds[i2][2], 0.0f);
            v3 += fmaxf(ds[i2][3], 0.0f);
        }
        *reinterpret_cast<float2*>(out0 + 8 * nt + 2 * qt) = make_float2(v0, v1);
        *reinterpret_cast<float2*>(out1 + 8 * nt + 2 * qt) = make_float2(v2, v3);
    }
}

// One layer, both groups, fully fused per n-tile.
// Ap* = h_{t-1}, As* = h_{t-2} (skip), An* = output slot (holds dead h_{t-3}).
template <bool HAS_SKIP, bool LAST>
__device__ __forceinline__ void layer_step(
    const Frag& Ap0, const Frag& As0, Frag& An0,
    const Frag& Ap1, const Frag& As1, Frag& An1,
    uint32_t wn, uint32_t ws,
    const float* __restrict__ bnp, const float* __restrict__ bsp,
    uint32_t soff0, uint32_t soff1, int qt,
    float* __restrict__ o00, float* __restrict__ o01,
    float* __restrict__ o10, float* __restrict__ o11)
{
#pragma unroll
    for (int np = 0; np < 4; ++np) {
        uint32_t B[2][8];
        float dn0[2][4], dn1[2][4], ds0[2][4], ds1[2][4];

        // ---- next GEMM (bias-initialized accumulators) ----
#pragma unroll
        for (int i2 = 0; i2 < 2; ++i2) {
            uint32_t a = wn + (uint32_t)(2 * np + i2) * 1024;
            LDSM_X4(&B[i2][0], a + soff0);
            LDSM_X4(&B[i2][4], a + soff1);
        }
#pragma unroll
        for (int i2 = 0; i2 < 2; ++i2) {
            float b0 = bnp[8 * (2 * np + i2) + 2 * qt];
            float b1 = bnp[8 * (2 * np + i2) + 2 * qt + 1];
            dn0[i2][0] = b0; dn0[i2][1] = b1; dn0[i2][2] = b0; dn0[i2][3] = b1;
            dn1[i2][0] = b0; dn1[i2][1] = b1; dn1[i2][2] = b0; dn1[i2][3] = b1;
        }
#pragma unroll
        for (int kt = 0; kt < 4; ++kt)
#pragma unroll
            for (int i2 = 0; i2 < 2; ++i2) {
                mma_f16(dn0[i2], Ap0.a[kt], B[i2][2 * kt], B[i2][2 * kt + 1]);
                mma_f16(dn1[i2], Ap1.a[kt], B[i2][2 * kt], B[i2][2 * kt + 1]);
            }

        // ---- skip GEMM (reuses B registers) ----
        if (HAS_SKIP) {
#pragma unroll
            for (int i2 = 0; i2 < 2; ++i2) {
                uint32_t s = ws + (uint32_t)(2 * np + i2) * 1024;
                LDSM_X4(&B[i2][0], s + soff0);
                LDSM_X4(&B[i2][4], s + soff1);
            }
#pragma unroll
            for (int i2 = 0; i2 < 2; ++i2) {
                float s0 = bsp[8 * (2 * np + i2) + 2 * qt];
                float s1 = bsp[8 * (2 * np + i2) + 2 * qt + 1];
                ds0[i2][0] = s0; ds0[i2][1] = s1; ds0[i2][2] = s0; ds0[i2][3] = s1;
                ds1[i2][0] = s0; ds1[i2][1] = s1; ds1[i2][2] = s0; ds1[i2][3] = s1;
            }
#pragma unroll
            for (int kt = 0; kt < 4; ++kt)
#pragma unroll
                for (int i2 = 0; i2 < 2; ++i2) {
                    mma_f16(ds0[i2], As0.a[kt], B[i2][2 * kt], B[i2][2 * kt + 1]);
                    mma_f16(ds1[i2], As1.a[kt], B[i2][2 * kt], B[i2][2 * kt + 1]);
                }
        }

        // ---- inline epilogue ----
        if (LAST) {
            epi_last<HAS_SKIP>(dn0, ds0, np, qt, o00, o01);
            epi_last<HAS_SKIP>(dn1, ds1, np, qt, o10, o11);
        } else {
            epi_h2<HAS_SKIP>(dn0, ds0, An0, np);
            epi_h2<HAS_SKIP>(dn1, ds1, An1, np);
        }
    }
}

// load 16 rows of x into a Frag (fp16)
__device__ __forceinline__ void load_x(const float* __restrict__ xr0,
                                       const float* __restrict__ xr1,
                                       Frag& A, int qt)
{
#pragma unroll
    for (int kt = 0; kt < 4; ++kt) {
        const int c = 16 * kt + 2 * qt;
        float2 p0 = *reinterpret_cast<const float2*>(xr0 + c);
        float2 p1 = *reinterpret_cast<const float2*>(xr1 + c);
        float2 p2 = *reinterpret_cast<const float2*>(xr0 + c + 8);
        float2 p3 = *reinterpret_cast<const float2*>(xr1 + c + 8);
        A.a[kt][0] = pk_h2(p0.x, p0.y);
        A.a[kt][1] = pk_h2(p1.x, p1.y);
        A.a[kt][2] = pk_h2(p2.x, p2.y);
        A.a[kt][3] = pk_h2(p3.x, p3.y);
    }
}

__global__ void __launch_bounds__(TPB, 1)
nn_mma_kernel(const float* __restrict__ x,
              const float* __restrict__ Wn_g,
              const float* __restrict__ bn_g,
              const float* __restrict__ Ws_g,
              const float* __restrict__ bs_g,
              float* __restrict__ out)
{
    extern __shared__ unsigned char sm[];
    const uint32_t smb = smem_to_u32(sm);
    const int tid  = threadIdx.x;
    const int wid  = tid >> 5;
    const int lane = tid & 31;
    const int qt   = lane & 3;
    const int grp  = lane >> 2;

    // ---- stage 13 weight matrices as fp16, [n][k] row-major, SW128 ----
    for (int idx = tid; idx < 13 * 4096; idx += TPB) {
        int mat = idx >> 12, e = idx & 4095;
        float v = (mat < 7) ? Wn_g[mat * 4096 + e] : Ws_g[(mat - 7) * 4096 + e];
        int n = e >> 6, k = e & 63;
        uint32_t sw = SMEM_SWIZZLE_128B((uint32_t)(n * 128 + k * 2));
        *reinterpret_cast<__half*>(sm + OFF_W + mat * 8192 + sw) = __float2half_rn(v);
    }
    for (int i = tid; i < 448; i += TPB)
        reinterpret_cast<float*>(sm + OFF_BN)[i] = bn_g[i];
    for (int i = tid; i < 384; i += TPB)
        reinterpret_cast<float*>(sm + OFF_BS)[i] = bs_g[i];
    __syncthreads();

    // per-thread ldmatrix.x4 swizzled offsets (k halves 0-31 / 32-63)
    const int r8 = lane & 7, b4 = lane >> 3;
    const uint32_t soff0 = (uint32_t)(r8 * 128 + ((b4 * 16)      ^ (r8 * 16)));
    const uint32_t soff1 = (uint32_t)(r8 * 128 + ((b4 * 16 + 64) ^ (r8 * 16)));

    const float* bn = reinterpret_cast<const float*>(sm + OFF_BN);
    const float* bs = reinterpret_cast<const float*>(sm + OFF_BS);
    const uint32_t w0 = smb + OFF_W;

    // warps independent: global warp-strided loop over 32-row macro-groups
    const int gw = blockIdx.x * (TPB / 32) + wid;

    for (int g = gw; g < NMAC; g += WSTEP) {
        const size_t r00 = (size_t)g * 32 + grp;       // group0 rows
        const size_t r01 = r00 + 8;
        const size_t r10 = r00 + 16;                   // group1 rows
        const size_t r11 = r00 + 24;

        // 3 slots per group: h_t lives in S[t % 3] (S0 starts as h0 = x)
        Frag S0g0, S1g0, S2g0, S0g1, S1g1, S2g1;
        load_x(x + r00 * 64, x + r01 * 64, S0g0, qt);
        load_x(x + r10 * 64, x + r11 * 64, S0g1, qt);

        float* o00 = out + r00 * 64;
        float* o01 = out + r01 * 64;
        float* o10 = out + r10 * 64;
        float* o11 = out + r11 * 64;

        // layer t: Ap = S[(t-1)%3], As = S[(t-2)%3], An = S[t%3] (dead h_{t-3})
        layer_step<false, false>(S0g0, S0g0, S1g0, S0g1, S0g1, S1g1,
                                 w0 + 0 * 8192, 0, bn + 0 * 64, bs,
                                 soff0, soff1, qt, o00, o01, o10, o11);          // h1->S1
        layer_step<true,  false>(S1g0, S0g0, S2g0, S1g1, S0g1, S2g1,
                                 w0 + 1 * 8192, w0 + 7 * 8192,
                                 bn + 1 * 64, bs + 0 * 64,
                                 soff0, soff1, qt, o00, o01, o10, o11);          // h2->S2
        layer_step<true,  false>(S2g0, S1g0, S0g0, S2g1, S1g1, S0g1,
                                 w0 + 2 * 8192, w0 + 8 * 8192,
                                 bn + 2 * 64, bs + 1 * 64,
                                 soff0, soff1, qt, o00, o01, o10, o11);          // h3->S0
        layer_step<true,  false>(S0g0, S2g0, S1g0, S0g1, S2g1, S1g1,
                                 w0 + 3 * 8192, w0 + 9 * 8192,
                                 bn + 3 * 64, bs + 2 * 64,
                                 soff0, soff1, qt, o00, o01, o10, o11);          // h4->S1
        layer_step<true,  false>(S1g0, S0g0, S2g0, S1g1, S0g1, S2g1,
                                 w0 + 4 * 8192, w0 + 10 * 8192,
                                 bn + 4 * 64, bs + 3 * 64,
                                 soff0, soff1, qt, o00, o01, o10, o11);          // h5->S2
        layer_step<true,  false>(S2g0, S1g0, S0g0, S2g1, S1g1, S0g1,
                                 w0 + 5 * 8192, w0 + 11 * 8192,
                                 bn + 5 * 64, bs + 4 * 64,
                                 soff0, soff1, qt, o00, o01, o10, o11);          // h6->S0
        layer_step<true,  true >(S0g0, S2g0, S1g0, S0g1, S2g1, S1g1,
                                 w0 + 6 * 8192, w0 + 12 * 8192,
                                 bn + 6 * 64, bs + 5 * 64,
                                 soff0, soff1, qt, o00, o01, o10, o11);          // h7->out
    }
}

extern "C" void kernel_launch(void* const* d_in, const int* in_sizes, int n_in,
                              void* d_out, int out_size)
{
    const float* x  = (const float*)d_in[0];
    const float* Wn = (const float*)d_in[1];
    const float* bn = (const float*)d_in[2];
    const float* Ws = (const float*)d_in[3];
    const float* bs = (const float*)d_in[4];
    float* out = (float*)d_out;

    cudaFuncSetAttribute(nn_mma_kernel,
                         cudaFuncAttributeMaxDynamicSharedMemorySize, SMEM_TOTAL);
    nn_mma_kernel<<<GRID, TPB, SMEM_TOTAL>>>(x, Wn, bn, Ws, bs, out);
}

// round 15
// speedup vs baseline: 2.1860x; 1.0254x over previous
#include <cuda_runtime.h>
#include <cuda_fp16.h>
#include <cstdint>

// NeuralNetwork_28819230556388 — B=262144, D=64, 13 chained 64x64 GEMMs.
// R15: R14 (fp16 single-product, 2 groups/warp, 3 slots/group, half2
// epilogue) + INTERLEAVED next+skip GEMM per n-tile: both B sets (Bn, Bs)
// preloaded, MMAs issued across 8 independent accumulator chains
// (dn0/dn1/ds0/ds1 x i2). Same-chain issue distance 4->8 instructions
// (kills RAW bubbles); skip-B LDSM latency hidden under next-MMAs.
// Arithmetic bit-identical to R14 (rel_err must stay 4.0948e-4).
// Bias-in-accumulator, weights SMEM-resident, persistent CTAs, no barriers.

#define TPB     256
#define GRID    148
#define NMAC    8192                  // 262144 / 32 rows per macro-group
#define WSTEP   (GRID * (TPB / 32))   // 1184 warps

// SMEM layout (bytes)
#define OFF_BN 0                      // 7*64 f32 = 1792
#define OFF_BS 1792                   // 6*64 f32 = 1536
#define OFF_W  4096                   // 13 mats * 8192 fp16
#define SMEM_TOTAL (4096 + 13*8192)   // 110592

#define SMEM_SWIZZLE_128B(bo) ((bo) ^ (((bo) >> 3) & 0x70))

__device__ __forceinline__ uint32_t smem_to_u32(const void* p) {
    uint32_t a;
    asm("{ .reg .u64 t; cvta.to.shared.u64 t, %1; cvt.u32.u64 %0, t; }"
        : "=r"(a) : "l"(p));
    return a;
}

#define LDSM_X4(r, addr) \
    asm volatile("ldmatrix.sync.aligned.m8n8.x4.shared.b16 {%0,%1,%2,%3}, [%4];" \
        : "=r"((r)[0]), "=r"((r)[1]), "=r"((r)[2]), "=r"((r)[3]) \
        : "r"(addr))

__device__ __forceinline__ void mma_f16(float d[4], const uint32_t a[4],
                                        uint32_t b0, uint32_t b1) {
    asm volatile(
        "mma.sync.aligned.m16n8k16.row.col.f32.f16.f16.f32 "
        "{%0,%1,%2,%3}, {%4,%5,%6,%7}, {%8,%9}, {%0,%1,%2,%3};"
        : "+f"(d[0]), "+f"(d[1]), "+f"(d[2]), "+f"(d[3])
        : "r"(a[0]), "r"(a[1]), "r"(a[2]), "r"(a[3]), "r"(b0), "r"(b1));
}

__device__ __forceinline__ uint32_t pk_h2(float a, float b) {
    __half2 h = __floats2half2_rn(a, b);
    return *reinterpret_cast<uint32_t*>(&h);
}

// 16 rows x 64 cols activation fragment, fp16 A-frags [ktile][reg]
struct Frag {
    uint32_t a[4][4];
};

// half2 epilogue for one group's np: An = hmax2(dn,0) [+ hmax2(ds,0)]
template <bool HAS_SKIP>
__device__ __forceinline__ void epi_h2(const float dn[2][4], const float ds[2][4],
                                       Frag& An, int np)
{
    const __half2 z = __float2half2_rn(0.0f);
#pragma unroll
    for (int i2 = 0; i2 < 2; ++i2) {
        __half2 n01 = __floats2half2_rn(dn[i2][0], dn[i2][1]);
        __half2 n23 = __floats2half2_rn(dn[i2][2], dn[i2][3]);
        n01 = __hmax2(n01, z);
        n23 = __hmax2(n23, z);
        if (HAS_SKIP) {
            __half2 s01 = __floats2half2_rn(ds[i2][0], ds[i2][1]);
            __half2 s23 = __floats2half2_rn(ds[i2][2], ds[i2][3]);
            n01 = __hadd2(n01, __hmax2(s01, z));
            n23 = __hadd2(n23, __hmax2(s23, z));
        }
        An.a[np][2 * i2]     = *reinterpret_cast<uint32_t*>(&n01);
        An.a[np][2 * i2 + 1] = *reinterpret_cast<uint32_t*>(&n23);
    }
}

// exact fp32 epilogue for the final layer (writes gmem)
template <bool HAS_SKIP>
__device__ __forceinline__ void epi_last(const float dn[2][4], const float ds[2][4],
                                         int np, int qt,
                                         float* __restrict__ out0,
                                         float* __restrict__ out1)
{
#pragma unroll
    for (int i2 = 0; i2 < 2; ++i2) {
        const int nt = 2 * np + i2;
        float v0 = fmaxf(dn[i2][0], 0.0f);
        float v1 = fmaxf(dn[i2][1], 0.0f);
        float v2 = fmaxf(dn[i2][2], 0.0f);
        float v3 = fmaxf(dn[i2][3], 0.0f);
        if (HAS_SKIP) {
            v0 += fmaxf(ds[i2][0], 0.0f);
            v1 += fmaxf(ds[i2][1], 0.0f);
            v2 += fmaxf(ds[i2][2], 0.0f);
            v3 += fmaxf(ds[i2][3], 0.0f);
        }
        *reinterpret_cast<float2*>(out0 + 8 * nt + 2 * qt) = make_float2(v0, v1);
        *reinterpret_cast<float2*>(out1 + 8 * nt + 2 * qt) = make_float2(v2, v3);
    }
}

// One layer, both groups, fused per n-tile, next+skip INTERLEAVED.
// Ap* = h_{t-1}, As* = h_{t-2} (skip), An* = output slot (holds dead h_{t-3}).
template <bool HAS_SKIP, bool LAST>
__device__ __forceinline__ void layer_step(
    const Frag& Ap0, const Frag& As0, Frag& An0,
    const Frag& Ap1, const Frag& As1, Frag& An1,
    uint32_t wn, uint32_t ws,
    const float* __restrict__ bnp, const float* __restrict__ bsp,
    uint32_t soff0, uint32_t soff1, int qt,
    float* __restrict__ o00, float* __restrict__ o01,
    float* __restrict__ o10, float* __restrict__ o11)
{
#pragma unroll
    for (int np = 0; np < 4; ++np) {
        uint32_t Bn[2][8], Bs[2][8];
        float dn0[2][4], dn1[2][4], ds0[2][4], ds1[2][4];

        // ---- load BOTH weight fragment sets up front ----
#pragma unroll
        for (int i2 = 0; i2 < 2; ++i2) {
            uint32_t a = wn + (uint32_t)(2 * np + i2) * 1024;
            LDSM_X4(&Bn[i2][0], a + soff0);
            LDSM_X4(&Bn[i2][4], a + soff1);
        }
        if (HAS_SKIP) {
#pragma unroll
            for (int i2 = 0; i2 < 2; ++i2) {
                uint32_t s = ws + (uint32_t)(2 * np + i2) * 1024;
                LDSM_X4(&Bs[i2][0], s + soff0);
                LDSM_X4(&Bs[i2][4], s + soff1);
            }
        }

        // ---- bias-initialized accumulators ----
#pragma unroll
        for (int i2 = 0; i2 < 2; ++i2) {
            float b0 = bnp[8 * (2 * np + i2) + 2 * qt];
            float b1 = bnp[8 * (2 * np + i2) + 2 * qt + 1];
            dn0[i2][0] = b0; dn0[i2][1] = b1; dn0[i2][2] = b0; dn0[i2][3] = b1;
            dn1[i2][0] = b0; dn1[i2][1] = b1; dn1[i2][2] = b0; dn1[i2][3] = b1;
            if (HAS_SKIP) {
                float s0 = bsp[8 * (2 * np + i2) + 2 * qt];
                float s1 = bsp[8 * (2 * np + i2) + 2 * qt + 1];
                ds0[i2][0] = s0; ds0[i2][1] = s1; ds0[i2][2] = s0; ds0[i2][3] = s1;
                ds1[i2][0] = s0; ds1[i2][1] = s1; ds1[i2][2] = s0; ds1[i2][3] = s1;
            }
        }

        // ---- interleaved MMA stream: 8 independent chains (4 if no skip) ----
#pragma unroll
        for (int kt = 0; kt < 4; ++kt)
#pragma unroll
            for (int i2 = 0; i2 < 2; ++i2) {
                mma_f16(dn0[i2], Ap0.a[kt], Bn[i2][2 * kt], Bn[i2][2 * kt + 1]);
                mma_f16(dn1[i2], Ap1.a[kt], Bn[i2][2 * kt], Bn[i2][2 * kt + 1]);
                if (HAS_SKIP) {
                    mma_f16(ds0[i2], As0.a[kt], Bs[i2][2 * kt], Bs[i2][2 * kt + 1]);
                    mma_f16(ds1[i2], As1.a[kt], Bs[i2][2 * kt], Bs[i2][2 * kt + 1]);
                }
            }

        // ---- inline epilogue ----
        if (LAST) {
            epi_last<HAS_SKIP>(dn0, ds0, np, qt, o00, o01);
            epi_last<HAS_SKIP>(dn1, ds1, np, qt, o10, o11);
        } else {
            epi_h2<HAS_SKIP>(dn0, ds0, An0, np);
            epi_h2<HAS_SKIP>(dn1, ds1, An1, np);
        }
    }
}

// load 16 rows of x into a Frag (fp16)
__device__ __forceinline__ void load_x(const float* __restrict__ xr0,
                                       const float* __restrict__ xr1,
                                       Frag& A, int qt)
{
#pragma unroll
    for (int kt = 0; kt < 4; ++kt) {
        const int c = 16 * kt + 2 * qt;
        float2 p0 = *reinterpret_cast<const float2*>(xr0 + c);
        float2 p1 = *reinterpret_cast<const float2*>(xr1 + c);
        float2 p2 = *reinterpret_cast<const float2*>(xr0 + c + 8);
        float2 p3 = *reinterpret_cast<const float2*>(xr1 + c + 8);
        A.a[kt][0] = pk_h2(p0.x, p0.y);
        A.a[kt][1] = pk_h2(p1.x, p1.y);
        A.a[kt][2] = pk_h2(p2.x, p2.y);
        A.a[kt][3] = pk_h2(p3.x, p3.y);
    }
}

__global__ void __launch_bounds__(TPB, 1)
nn_mma_kernel(const float* __restrict__ x,
              const float* __restrict__ Wn_g,
              const float* __restrict__ bn_g,
              const float* __restrict__ Ws_g,
              const float* __restrict__ bs_g,
              float* __restrict__ out)
{
    extern __shared__ unsigned char sm[];
    const uint32_t smb = smem_to_u32(sm);
    const int tid  = threadIdx.x;
    const int wid  = tid >> 5;
    const int lane = tid & 31;
    const int qt   = lane & 3;
    const int grp  = lane >> 2;

    // ---- stage 13 weight matrices as fp16, [n][k] row-major, SW128 ----
    for (int idx = tid; idx < 13 * 4096; idx += TPB) {
        int mat = idx >> 12, e = idx & 4095;
        float v = (mat < 7) ? Wn_g[mat * 4096 + e] : Ws_g[(mat - 7) * 4096 + e];
        int n = e >> 6, k = e & 63;
        uint32_t sw = SMEM_SWIZZLE_128B((uint32_t)(n * 128 + k * 2));
        *reinterpret_cast<__half*>(sm + OFF_W + mat * 8192 + sw) = __float2half_rn(v);
    }
    for (int i = tid; i < 448; i += TPB)
        reinterpret_cast<float*>(sm + OFF_BN)[i] = bn_g[i];
    for (int i = tid; i < 384; i += TPB)
        reinterpret_cast<float*>(sm + OFF_BS)[i] = bs_g[i];
    __syncthreads();

    // per-thread ldmatrix.x4 swizzled offsets (k halves 0-31 / 32-63)
    const int r8 = lane & 7, b4 = lane >> 3;
    const uint32_t soff0 = (uint32_t)(r8 * 128 + ((b4 * 16)      ^ (r8 * 16)));
    const uint32_t soff1 = (uint32_t)(r8 * 128 + ((b4 * 16 + 64) ^ (r8 * 16)));

    const float* bn = reinterpret_cast<const float*>(sm + OFF_BN);
    const float* bs = reinterpret_cast<const float*>(sm + OFF_BS);
    const uint32_t w0 = smb + OFF_W;

    // warps independent: global warp-strided loop over 32-row macro-groups
    const int gw = blockIdx.x * (TPB / 32) + wid;

    for (int g = gw; g < NMAC; g += WSTEP) {
        const size_t r00 = (size_t)g * 32 + grp;       // group0 rows
        const size_t r01 = r00 + 8;
        const size_t r10 = r00 + 16;                   // group1 rows
        const size_t r11 = r00 + 24;

        // 3 slots per group: h_t lives in S[t % 3] (S0 starts as h0 = x)
        Frag S0g0, S1g0, S2g0, S0g1, S1g1, S2g1;
        load_x(x + r00 * 64, x + r01 * 64, S0g0, qt);
        load_x(x + r10 * 64, x + r11 * 64, S0g1, qt);

        float* o00 = out + r00 * 64;
        float* o01 = out + r01 * 64;
        float* o10 = out + r10 * 64;
        float* o11 = out + r11 * 64;

        // layer t: Ap = S[(t-1)%3], As = S[(t-2)%3], An = S[t%3] (dead h_{t-3})
        layer_step<false, false>(S0g0, S0g0, S1g0, S0g1, S0g1, S1g1,
                                 w0 + 0 * 8192, 0, bn + 0 * 64, bs,
                                 soff0, soff1, qt, o00, o01, o10, o11);          // h1->S1
        layer_step<true,  false>(S1g0, S0g0, S2g0, S1g1, S0g1, S2g1,
                                 w0 + 1 * 8192, w0 + 7 * 8192,
                                 bn + 1 * 64, bs + 0 * 64,
                                 soff0, soff1, qt, o00, o01, o10, o11);          // h2->S2
        layer_step<true,  false>(S2g0, S1g0, S0g0, S2g1, S1g1, S0g1,
                                 w0 + 2 * 8192, w0 + 8 * 8192,
                                 bn + 2 * 64, bs + 1 * 64,
                                 soff0, soff1, qt, o00, o01, o10, o11);          // h3->S0
        layer_step<true,  false>(S0g0, S2g0, S1g0, S0g1, S2g1, S1g1,
                                 w0 + 3 * 8192, w0 + 9 * 8192,
                                 bn + 3 * 64, bs + 2 * 64,
                                 soff0, soff1, qt, o00, o01, o10, o11);          // h4->S1
        layer_step<true,  false>(S1g0, S0g0, S2g0, S1g1, S0g1, S2g1,
                                 w0 + 4 * 8192, w0 + 10 * 8192,
                                 bn + 4 * 64, bs + 3 * 64,
                                 soff0, soff1, qt, o00, o01, o10, o11);          // h5->S2
        layer_step<true,  false>(S2g0, S1g0, S0g0, S2g1, S1g1, S0g1,
                                 w0 + 5 * 8192, w0 + 11 * 8192,
                                 bn + 5 * 64, bs + 4 * 64,
                                 soff0, soff1, qt, o00, o01, o10, o11);          // h6->S0
        layer_step<true,  true >(S0g0, S2g0, S1g0, S0g1, S2g1, S1g1,
                                 w0 + 6 * 8192, w0 + 12 * 8192,
                                 bn + 6 * 64, bs + 5 * 64,
                                 soff0, soff1, qt, o00, o01, o10, o11);          // h7->out
    }
}

extern "C" void kernel_launch(void* const* d_in, const int* in_sizes, int n_in,
                              void* d_out, int out_size)
{
    const float* x  = (const float*)d_in[0];
    const float* Wn = (const float*)d_in[1];
    const float* bn = (const float*)d_in[2];
    const float* Ws = (const float*)d_in[3];
    const float* bs = (const float*)d_in[4];
    float* out = (float*)d_out;

    cudaFuncSetAttribute(nn_mma_kernel,
                         cudaFuncAttributeMaxDynamicSharedMemorySize, SMEM_TOTAL);
    nn_mma_kernel<<<GRID, TPB, SMEM_TOTAL>>>(x, Wn, bn, Ws, bs, out);
}